// round 16
// baseline (speedup 1.0000x reference)
#include <cuda_runtime.h>
#include <cuda_bf16.h>
#include <cuda_fp16.h>
#include <math.h>
#include <stdint.h>

// Problem constants (fixed by the dataset)
#define N_NODES   100000
#define N_EDGES   1600000
#define IN_F      256
#define OUT_F     256
#define D_LABEL   32
#define ALPHA     0.2f
#define EPS_RS    1e-9f

#define SCAN_BLK  512

// Scratch (device globals: allowed; no cudaMalloc anywhere)
__device__ __half g_Wh_h[(size_t)N_NODES * OUT_F];   // ~50 MB (fp16 Wh)
__device__ __half g_h16[(size_t)N_NODES * IN_F];     // ~50 MB (fp16 input h)
__device__ float g_att[N_EDGES];
__device__ int   g_deg[N_NODES];
__device__ int   g_rowstart[N_NODES];
__device__ int   g_cursor[N_NODES];
__device__ int   g_edst[N_EDGES];
__device__ int   g_bsum[256];
// W transposed, fp16: Wt[n][k] = W[k][n]
__device__ __half g_Wt16[256 * 256];

// ---------------------------------------------------------------------------
// helpers
// ---------------------------------------------------------------------------
__device__ __forceinline__ uint32_t smem_u32(const void* p) {
    uint32_t a;
    asm("{ .reg .u64 t; cvta.to.shared.u64 t, %1; cvt.u32.u64 %0, t; }"
        : "=r"(a) : "l"(p));
    return a;
}

__device__ __forceinline__ void ldsm_x4(uint32_t* r, uint32_t addr) {
    asm volatile("ldmatrix.sync.aligned.m8n8.x4.shared.b16 {%0,%1,%2,%3}, [%4];"
                 : "=r"(r[0]), "=r"(r[1]), "=r"(r[2]), "=r"(r[3]) : "r"(addr));
}
__device__ __forceinline__ void mma_fp16(float* c, const uint32_t* a, const uint32_t* b) {
    asm volatile(
        "mma.sync.aligned.m16n8k16.row.col.f32.f16.f16.f32 "
        "{%0,%1,%2,%3}, {%4,%5,%6,%7}, {%8,%9}, {%0,%1,%2,%3};"
        : "+f"(c[0]), "+f"(c[1]), "+f"(c[2]), "+f"(c[3])
        : "r"(a[0]), "r"(a[1]), "r"(a[2]), "r"(a[3]), "r"(b[0]), "r"(b[1]));
}

// ---------------------------------------------------------------------------
// Kernel 0: zero degree array
// ---------------------------------------------------------------------------
__global__ void k_zero_deg(int n) {
    int i = blockIdx.x * blockDim.x + threadIdx.x;
    if (i < n) g_deg[i] = 0;
}

// ---------------------------------------------------------------------------
// Kernel P1: W [K,N] fp32 -> Wt16 [N,K] fp16
// ---------------------------------------------------------------------------
__global__ void k_prep_W(const float* __restrict__ W) {
    int i = blockIdx.x * 256 + threadIdx.x;     // 0..65535
    int n = i >> 8, k = i & 255;
    g_Wt16[n * 256 + k] = __float2half_rn(W[k * 256 + n]);
}

// ---------------------------------------------------------------------------
// Kernel P2: h [N,256] fp32 -> g_h16 fp16 (8 elems / thread, streaming)
// ---------------------------------------------------------------------------
__global__ void k_prep_h16(const float* __restrict__ h, int total8) {
    int i = blockIdx.x * 256 + threadIdx.x;     // each handles 8 floats
    if (i < total8) {
        const float* p = h + (size_t)i * 8;
        float4 a = __ldcs((const float4*)p);
        float4 b = __ldcs((const float4*)(p + 4));
        __half2 p0 = __floats2half2_rn(a.x, a.y);
        __half2 p1 = __floats2half2_rn(a.z, a.w);
        __half2 p2 = __floats2half2_rn(b.x, b.y);
        __half2 p3 = __floats2half2_rn(b.z, b.w);
        uint4 v;
        v.x = *(uint32_t*)&p0; v.y = *(uint32_t*)&p1;
        v.z = *(uint32_t*)&p2; v.w = *(uint32_t*)&p3;
        __stcs((uint4*)(g_h16 + (size_t)i * 8), v);
    }
}

// ---------------------------------------------------------------------------
// Kernel 1: HMMA GEMM  Wh = h16 @ Wt16, pure fp16 operands, fp32 accum.
// CTA 128M x 256N, 512 threads (warp grid 4x4, warp tile 32x64), A read once
// (fp16, no in-loop conversion), both operands chunk-staged, double-buffered.
// ---------------------------------------------------------------------------
#define C_ROW 80
#define ST_A  0                    // A 128*80 = 10240
#define ST_B  10240                // B 256*80 = 20480
#define STAGE_SZ 30720
#define GSM_TOTAL (2 * STAGE_SZ)   // 61440

__global__ __launch_bounds__(512, 1) void k_gemm_mma(int M)
{
    extern __shared__ __align__(16) char sm[];
    const uint32_t sbase = smem_u32(sm);
    const int tid  = threadIdx.x;
    const int lane = tid & 31;
    const int wid  = tid >> 5;          // 0..15
    const int wm   = wid >> 2;          // 0..3
    const int wn   = wid & 3;           // 0..3
    const int rowBase = blockIdx.y * 128;

    float acc[2][8][4];
#pragma unroll
    for (int i = 0; i < 2; i++)
#pragma unroll
        for (int j = 0; j < 8; j++)
#pragma unroll
            for (int q = 0; q < 4; q++) acc[i][j][q] = 0.0f;

    // ---- A fill mapping: thread -> (row, 16B quarter of 64B chunk-row)
    const int ar = tid >> 2;            // 0..127
    const int aq = tid & 3;             // 0..3 (8 halves = 16B)
    const int grow = rowBase + ar;
    const __half* aptr = g_h16 + (size_t)grow * IN_F + aq * 8;

    // ---- B fill mapping: 2 slots per thread
    const int bn0 = tid >> 2;           // 0..127
    const int bn1 = (tid + 512) >> 2;   // 128..255
    const int bq  = tid & 3;

    // prefetch chunk 0
    uint4 pfA = make_uint4(0u, 0u, 0u, 0u);
    if (grow < M) pfA = *(const uint4*)aptr;
    uint4 pfB0 = *(const uint4*)((const char*)g_Wt16 + (size_t)bn0 * 512 + bq * 16);
    uint4 pfB1 = *(const uint4*)((const char*)g_Wt16 + (size_t)bn1 * 512 + bq * 16);

    const uint32_t a_frag_off = (uint32_t)((wm * 32 + (lane & 15)) * C_ROW + (lane >> 4) * 16);
    const uint32_t b4_frag_off = (uint32_t)(
        (wn * 64 + (lane & 7) + ((lane >> 4) & 1) * 8) * C_ROW + ((lane >> 3) & 1) * 16);
    const uint32_t a_sts = (uint32_t)(ar * C_ROW + aq * 16);
    const uint32_t b_sts0 = (uint32_t)(bn0 * C_ROW + bq * 16);
    const uint32_t b_sts1 = (uint32_t)(bn1 * C_ROW + bq * 16);

    for (int c = 0; c < 8; c++) {
        const int stage = c & 1;
        char* stg = sm + stage * STAGE_SZ;
        *(uint4*)(stg + ST_A + a_sts)  = pfA;
        *(uint4*)(stg + ST_B + b_sts0) = pfB0;
        *(uint4*)(stg + ST_B + b_sts1) = pfB1;
        __syncthreads();

        if (c < 7) {
            if (grow < M) pfA = *(const uint4*)(aptr + (c + 1) * 32);
            pfB0 = *(const uint4*)((const char*)g_Wt16 + (size_t)bn0 * 512 + (c + 1) * 64 + bq * 16);
            pfB1 = *(const uint4*)((const char*)g_Wt16 + (size_t)bn1 * 512 + (c + 1) * 64 + bq * 16);
        }

        const uint32_t aB = sbase + stage * STAGE_SZ + a_frag_off;
        const uint32_t bB = sbase + stage * STAGE_SZ + b4_frag_off;
#pragma unroll
        for (int ks = 0; ks < 2; ks++) {
            uint32_t ahf[2][4];
#pragma unroll
            for (int mf = 0; mf < 2; mf++)
                ldsm_x4(ahf[mf], aB + ST_A + mf * (16 * C_ROW) + ks * 32);
#pragma unroll
            for (int p = 0; p < 4; p++) {
                uint32_t b4[4];
                ldsm_x4(b4, bB + ST_B + p * (16 * C_ROW) + ks * 32);
#pragma unroll
                for (int mf = 0; mf < 2; mf++)
#pragma unroll
                    for (int h = 0; h < 2; h++)
                        mma_fp16(acc[mf][2 * p + h], ahf[mf], &b4[h * 2]);
            }
        }
        __syncthreads();
    }

    // epilogue -> fp16
#pragma unroll
    for (int mf = 0; mf < 2; mf++) {
        int r0 = rowBase + wm * 32 + mf * 16 + (lane >> 2);
#pragma unroll
        for (int nf = 0; nf < 8; nf++) {
            int col = wn * 64 + nf * 8 + 2 * (lane & 3);
            if (r0 < M)
                *(__half2*)(g_Wh_h + (size_t)r0 * OUT_F + col) =
                    __floats2half2_rn(acc[mf][nf][0], acc[mf][nf][1]);
            if (r0 + 8 < M)
                *(__half2*)(g_Wh_h + (size_t)(r0 + 8) * OUT_F + col) =
                    __floats2half2_rn(acc[mf][nf][2], acc[mf][nf][3]);
        }
    }
}

// ---------------------------------------------------------------------------
// Kernel 2: degree histogram over src   (adj is INT32: [2, E] row-major)
// ---------------------------------------------------------------------------
__global__ void k_count(const int* __restrict__ adj, int E) {
    int e = blockIdx.x * blockDim.x + threadIdx.x;
    if (e < E) atomicAdd(&g_deg[adj[e]], 1);
}

// ---------------------------------------------------------------------------
// Kernels 3-5: exclusive scan of g_deg -> g_rowstart (and g_cursor copy)
// ---------------------------------------------------------------------------
__global__ void k_scan1(int n) {
    __shared__ int sm[SCAN_BLK];
    int i = blockIdx.x * SCAN_BLK + threadIdx.x;
    int v = (i < n) ? g_deg[i] : 0;
    sm[threadIdx.x] = v;
    __syncthreads();
    for (int off = 1; off < SCAN_BLK; off <<= 1) {
        int add = (threadIdx.x >= off) ? sm[threadIdx.x - off] : 0;
        __syncthreads();
        sm[threadIdx.x] += add;
        __syncthreads();
    }
    if (i < n) g_rowstart[i] = sm[threadIdx.x] - v;
    if (threadIdx.x == SCAN_BLK - 1) g_bsum[blockIdx.x] = sm[SCAN_BLK - 1];
}

__global__ void k_scan2(int nb) {
    __shared__ int sm[256];
    int t = threadIdx.x;
    int v = (t < nb) ? g_bsum[t] : 0;
    sm[t] = v;
    __syncthreads();
    for (int off = 1; off < 256; off <<= 1) {
        int add = (t >= off) ? sm[t - off] : 0;
        __syncthreads();
        sm[t] += add;
        __syncthreads();
    }
    if (t < nb) g_bsum[t] = sm[t] - v;
}

__global__ void k_scan3(int n) {
    int i = blockIdx.x * blockDim.x + threadIdx.x;
    if (i < n) {
        int rs = g_rowstart[i] + g_bsum[i >> 9];
        g_rowstart[i] = rs;
        g_cursor[i]   = rs;
    }
}

// ---------------------------------------------------------------------------
// Kernel 6: scatter edges into CSR (dst per slot)
// ---------------------------------------------------------------------------
__global__ void k_scatter(const int* __restrict__ adj, int E) {
    int e = blockIdx.x * blockDim.x + threadIdx.x;
    if (e < E) {
        int s = adj[e];
        int d = adj[E + e];
        int p = atomicAdd(&g_cursor[s], 1);
        g_edst[p] = d;
    }
}

// ---------------------------------------------------------------------------
// Kernel 7a: warp-per-node attention -> normalized weights in g_att
// ---------------------------------------------------------------------------
__global__ __launch_bounds__(256) void k_attention(
    const float* __restrict__ label,   // [N, 32]
    int n)
{
    const int wl   = threadIdx.x >> 5;
    const int lane = threadIdx.x & 31;
    const int w    = blockIdx.x * 8 + wl;
    if (w >= n) return;

    const float labi = label[(size_t)w * D_LABEL + lane];
    const int start = g_rowstart[w];
    const int d     = g_deg[w];

    float denom = 0.0f;
    int k = 0;
    for (; k + 1 < d; k += 2) {
        int j0 = __ldg(g_edst + start + k);
        int j1 = __ldg(g_edst + start + k + 1);
        float v0 = labi * __ldg(label + (size_t)j0 * D_LABEL + lane);
        float v1 = labi * __ldg(label + (size_t)j1 * D_LABEL + lane);
#pragma unroll
        for (int o = 16; o > 0; o >>= 1) {
            v0 += __shfl_xor_sync(0xffffffffu, v0, o);
            v1 += __shfl_xor_sync(0xffffffffu, v1, o);
        }
        float e0 = (v0 >= 0.0f) ? v0 : ALPHA * v0;
        float e1 = (v1 >= 0.0f) ? v1 : ALPHA * v1;
        float ex0 = __expf(e0);
        float ex1 = __expf(e1);
        denom += ex0 + ex1;
        if (lane == (k & 31))       g_att[start + k]     = ex0;
        if (lane == ((k + 1) & 31)) g_att[start + k + 1] = ex1;
    }
    if (k < d) {
        int j0 = __ldg(g_edst + start + k);
        float v0 = labi * __ldg(label + (size_t)j0 * D_LABEL + lane);
#pragma unroll
        for (int o = 16; o > 0; o >>= 1)
            v0 += __shfl_xor_sync(0xffffffffu, v0, o);
        float e0 = (v0 >= 0.0f) ? v0 : ALPHA * v0;
        float ex0 = __expf(e0);
        denom += ex0;
        if (lane == (k & 31)) g_att[start + k] = ex0;
    }
    const float inv = 1.0f / fmaxf(denom, EPS_RS);
    for (int t = lane; t < d; t += 32)
        g_att[start + t] *= inv;
}

// ---------------------------------------------------------------------------
// Kernel 7b: gather — R14 exact form (best: 259.3us total config)
// ---------------------------------------------------------------------------
__device__ __forceinline__ void fma8_h(float* acc, uint4 v, float a) {
    float2 f;
    f = __half22float2(*(__half2*)&v.x);
    acc[0] = fmaf(a, f.x, acc[0]); acc[1] = fmaf(a, f.y, acc[1]);
    f = __half22float2(*((__half2*)&v.x + 1));
    acc[2] = fmaf(a, f.x, acc[2]); acc[3] = fmaf(a, f.y, acc[3]);
    f = __half22float2(*(__half2*)&v.z);
    acc[4] = fmaf(a, f.x, acc[4]); acc[5] = fmaf(a, f.y, acc[5]);
    f = __half22float2(*((__half2*)&v.z + 1));
    acc[6] = fmaf(a, f.x, acc[6]); acc[7] = fmaf(a, f.y, acc[7]);
}

__global__ __launch_bounds__(256) void k_gather(
    float* __restrict__ out,   // [N, 256]
    int n)
{
    const int w    = blockIdx.x * 8 + (threadIdx.x >> 5);
    const int lane = threadIdx.x & 31;
    if (w >= n) return;

    const int start = g_rowstart[w];
    const int d     = g_deg[w];
    const __half* base = g_Wh_h + lane * 8;   // 16B per lane, 512B per warp row

    float acc[8];
#pragma unroll
    for (int q = 0; q < 8; q++) acc[q] = 0.0f;

    int k = 0;
    for (; k + 7 < d; k += 8) {
        int   j[8];
        float a[8];
        uint4 v[8];
#pragma unroll
        for (int u = 0; u < 8; u++) j[u] = __ldg(g_edst + start + k + u);
#pragma unroll
        for (int u = 0; u < 8; u++) a[u] = __ldg(g_att + start + k + u);
#pragma unroll
        for (int u = 0; u < 8; u++)
            v[u] = __ldg((const uint4*)(base + (size_t)j[u] * OUT_F));
#pragma unroll
        for (int u = 0; u < 8; u++) fma8_h(acc, v[u], a[u]);
    }
    for (; k + 3 < d; k += 4) {
        int j0 = __ldg(g_edst + start + k);
        int j1 = __ldg(g_edst + start + k + 1);
        int j2 = __ldg(g_edst + start + k + 2);
        int j3 = __ldg(g_edst + start + k + 3);
        float a0 = __ldg(g_att + start + k);
        float a1 = __ldg(g_att + start + k + 1);
        float a2 = __ldg(g_att + start + k + 2);
        float a3 = __ldg(g_att + start + k + 3);
        uint4 v0 = __ldg((const uint4*)(base + (size_t)j0 * OUT_F));
        uint4 v1 = __ldg((const uint4*)(base + (size_t)j1 * OUT_F));
        uint4 v2 = __ldg((const uint4*)(base + (size_t)j2 * OUT_F));
        uint4 v3 = __ldg((const uint4*)(base + (size_t)j3 * OUT_F));
        fma8_h(acc, v0, a0);
        fma8_h(acc, v1, a1);
        fma8_h(acc, v2, a2);
        fma8_h(acc, v3, a3);
    }
    for (; k < d; k++) {
        int j0 = __ldg(g_edst + start + k);
        float a0 = __ldg(g_att + start + k);
        uint4 v0 = __ldg((const uint4*)(base + (size_t)j0 * OUT_F));
        fma8_h(acc, v0, a0);
    }

    float* o = out + (size_t)w * OUT_F + lane * 8;
    __stcs((float4*)(o + 0), make_float4(acc[0], acc[1], acc[2], acc[3]));
    __stcs((float4*)(o + 4), make_float4(acc[4], acc[5], acc[6], acc[7]));
}

// ---------------------------------------------------------------------------
// Launch — stream fork: branch A = prep_W + prep_h16 + GEMM (default stream),
//                        branch B = CSR build + attention (s2), join -> gather
// ---------------------------------------------------------------------------
extern "C" void kernel_launch(void* const* d_in, const int* in_sizes, int n_in,
                              void* d_out, int out_size)
{
    const float* h     = (const float*)d_in[0];   // [N, 256] fp32
    const float* label = (const float*)d_in[1];   // [N, 32]  fp32
    const float* W     = (const float*)d_in[2];   // [256, 256] fp32
    const int*   adj   = (const int*)d_in[3];     // [2, E] int32
    float*       out   = (float*)d_out;

    const int N = in_sizes[0] / IN_F;      // 100000
    const int E = in_sizes[3] / 2;         // 1600000

    const int T = 256;
    const int gbN = (N + T - 1) / T;
    const int gbE = (E + T - 1) / T;

    static cudaStream_t s2 = nullptr;
    static cudaEvent_t  evF = nullptr, evJ = nullptr;
    if (s2 == nullptr) {
        cudaFuncSetAttribute(k_gemm_mma, cudaFuncAttributeMaxDynamicSharedMemorySize, GSM_TOTAL);
        cudaStreamCreateWithFlags(&s2, cudaStreamNonBlocking);
        cudaEventCreateWithFlags(&evF, cudaEventDisableTiming);
        cudaEventCreateWithFlags(&evJ, cudaEventDisableTiming);
    }

    // fork
    cudaEventRecord(evF, 0);
    cudaStreamWaitEvent(s2, evF, 0);

    // ---- branch B (s2): CSR build + attention weights
    k_zero_deg<<<gbN, T, 0, s2>>>(N);
    k_count<<<gbE, T, 0, s2>>>(adj, E);
    int nb = (N + SCAN_BLK - 1) / SCAN_BLK;
    k_scan1<<<nb, SCAN_BLK, 0, s2>>>(N);
    k_scan2<<<1, 256, 0, s2>>>(nb);
    k_scan3<<<gbN, T, 0, s2>>>(N);
    k_scatter<<<gbE, T, 0, s2>>>(adj, E);
    k_attention<<<(N + 7) / 8, 256, 0, s2>>>(label, N);
    cudaEventRecord(evJ, s2);

    // ---- branch A (default stream): h->fp16, W prep, then pure-fp16 GEMM
    k_prep_W<<<256, 256>>>(W);
    int total8 = N * IN_F / 8;
    k_prep_h16<<<(total8 + 255) / 256, 256>>>(h, total8);
    dim3 ggrid(1, (N + 127) / 128);
    k_gemm_mma<<<ggrid, 512, GSM_TOTAL>>>(N);

    // join, then gather
    cudaStreamWaitEvent(0, evJ, 0);
    k_gather<<<(N + 7) / 8, 256>>>(out, N);
}

// round 17
// speedup vs baseline: 1.0966x; 1.0966x over previous
#include <cuda_runtime.h>
#include <cuda_bf16.h>
#include <cuda_fp16.h>
#include <math.h>
#include <stdint.h>

// Problem constants (fixed by the dataset)
#define N_NODES   100000
#define N_EDGES   1600000
#define IN_F      256
#define OUT_F     256
#define D_LABEL   32
#define ALPHA     0.2f
#define EPS_RS    1e-9f

#define SCAN_BLK  512

// Scratch (device globals: allowed; no cudaMalloc anywhere)
__device__ __half g_Wh_h[(size_t)N_NODES * OUT_F];   // ~50 MB (fp16 Wh)
__device__ float g_att[N_EDGES];
__device__ int   g_deg[N_NODES];
__device__ int   g_rowstart[N_NODES];
__device__ int   g_cursor[N_NODES];
__device__ int   g_edst[N_EDGES];
__device__ int   g_bsum[256];
// W transposed, fp16: Wt[n][k] = W[k][n]
__device__ __half g_Wt16[256 * 256];

// ---------------------------------------------------------------------------
// helpers
// ---------------------------------------------------------------------------
__device__ __forceinline__ uint32_t smem_u32(const void* p) {
    uint32_t a;
    asm("{ .reg .u64 t; cvta.to.shared.u64 t, %1; cvt.u32.u64 %0, t; }"
        : "=r"(a) : "l"(p));
    return a;
}

__device__ __forceinline__ void ldsm_x4(uint32_t* r, uint32_t addr) {
    asm volatile("ldmatrix.sync.aligned.m8n8.x4.shared.b16 {%0,%1,%2,%3}, [%4];"
                 : "=r"(r[0]), "=r"(r[1]), "=r"(r[2]), "=r"(r[3]) : "r"(addr));
}
__device__ __forceinline__ void mma_fp16(float* c, const uint32_t* a, const uint32_t* b) {
    asm volatile(
        "mma.sync.aligned.m16n8k16.row.col.f32.f16.f16.f32 "
        "{%0,%1,%2,%3}, {%4,%5,%6,%7}, {%8,%9}, {%0,%1,%2,%3};"
        : "+f"(c[0]), "+f"(c[1]), "+f"(c[2]), "+f"(c[3])
        : "r"(a[0]), "r"(a[1]), "r"(a[2]), "r"(a[3]), "r"(b[0]), "r"(b[1]));
}

// ---------------------------------------------------------------------------
// Kernel 0: zero degree array
// ---------------------------------------------------------------------------
__global__ void k_zero_deg(int n) {
    int i = blockIdx.x * blockDim.x + threadIdx.x;
    if (i < n) g_deg[i] = 0;
}

// ---------------------------------------------------------------------------
// Kernel P: W [K,N] fp32 -> Wt16 [N,K] fp16
// ---------------------------------------------------------------------------
__global__ void k_prep_W(const float* __restrict__ W) {
    int i = blockIdx.x * 256 + threadIdx.x;     // 0..65535
    int n = i >> 8, k = i & 255;
    g_Wt16[n * 256 + k] = __float2half_rn(W[k * 256 + n]);
}

// ---------------------------------------------------------------------------
// Kernel 1: HMMA GEMM (R14 exact): A fp32->fp16 in-loop, B fp16, fp32 accum.
// CTA 128M x 256N, 512 threads (warp grid 4x4, warp tile 32x64), A read once,
// both operands chunk-staged (K chunks of 32), double-buffered. smem 60KB.
// ---------------------------------------------------------------------------
#define C_ROW 80
#define ST_A  0                    // A 128*80 = 10240
#define ST_B  10240                // B 256*80 = 20480
#define STAGE_SZ 30720
#define GSM_TOTAL (2 * STAGE_SZ)   // 61440

__global__ __launch_bounds__(512, 1) void k_gemm_mma(const float* __restrict__ A, int M)
{
    extern __shared__ __align__(16) char sm[];
    const uint32_t sbase = smem_u32(sm);
    const int tid  = threadIdx.x;
    const int lane = tid & 31;
    const int wid  = tid >> 5;          // 0..15
    const int wm   = wid >> 2;          // 0..3
    const int wn   = wid & 3;           // 0..3
    const int rowBase = blockIdx.y * 128;

    float acc[2][8][4];
#pragma unroll
    for (int i = 0; i < 2; i++)
#pragma unroll
        for (int j = 0; j < 8; j++)
#pragma unroll
            for (int q = 0; q < 4; q++) acc[i][j][q] = 0.0f;

    const int ar = tid >> 2;            // 0..127
    const int aq = tid & 3;             // 0..3 (8 floats -> 8 fp16 = 16B)
    const int grow = rowBase + ar;
    const float* aptr = A + (size_t)grow * IN_F + aq * 8;

    const int bn0 = tid >> 2;           // 0..127
    const int bn1 = (tid + 512) >> 2;   // 128..255
    const int bq  = tid & 3;

    float4 pfA0 = make_float4(0.f,0.f,0.f,0.f), pfA1 = pfA0;
    if (grow < M) {
        pfA0 = *(const float4*)(aptr + 0);
        pfA1 = *(const float4*)(aptr + 4);
    }
    uint4 pfB0 = *(const uint4*)((const char*)g_Wt16 + (size_t)bn0 * 512 + bq * 16);
    uint4 pfB1 = *(const uint4*)((const char*)g_Wt16 + (size_t)bn1 * 512 + bq * 16);

    const uint32_t a_frag_off = (uint32_t)((wm * 32 + (lane & 15)) * C_ROW + (lane >> 4) * 16);
    const uint32_t b4_frag_off = (uint32_t)(
        (wn * 64 + (lane & 7) + ((lane >> 4) & 1) * 8) * C_ROW + ((lane >> 3) & 1) * 16);
    const uint32_t a_sts = (uint32_t)(ar * C_ROW + aq * 16);
    const uint32_t b_sts0 = (uint32_t)(bn0 * C_ROW + bq * 16);
    const uint32_t b_sts1 = (uint32_t)(bn1 * C_ROW + bq * 16);

    for (int c = 0; c < 8; c++) {
        const int stage = c & 1;
        char* stg = sm + stage * STAGE_SZ;
        {
            __half2 p0 = __floats2half2_rn(pfA0.x, pfA0.y);
            __half2 p1 = __floats2half2_rn(pfA0.z, pfA0.w);
            __half2 p2 = __floats2half2_rn(pfA1.x, pfA1.y);
            __half2 p3 = __floats2half2_rn(pfA1.z, pfA1.w);
            uint4 v;
            v.x = *(uint32_t*)&p0; v.y = *(uint32_t*)&p1;
            v.z = *(uint32_t*)&p2; v.w = *(uint32_t*)&p3;
            *(uint4*)(stg + ST_A + a_sts) = v;
        }
        *(uint4*)(stg + ST_B + b_sts0) = pfB0;
        *(uint4*)(stg + ST_B + b_sts1) = pfB1;
        __syncthreads();

        if (c < 7) {
            if (grow < M) {
                pfA0 = *(const float4*)(aptr + (c + 1) * 32 + 0);
                pfA1 = *(const float4*)(aptr + (c + 1) * 32 + 4);
            }
            pfB0 = *(const uint4*)((const char*)g_Wt16 + (size_t)bn0 * 512 + (c + 1) * 64 + bq * 16);
            pfB1 = *(const uint4*)((const char*)g_Wt16 + (size_t)bn1 * 512 + (c + 1) * 64 + bq * 16);
        }

        const uint32_t aB = sbase + stage * STAGE_SZ + a_frag_off;
        const uint32_t bB = sbase + stage * STAGE_SZ + b4_frag_off;
#pragma unroll
        for (int ks = 0; ks < 2; ks++) {
            uint32_t ahf[2][4];
#pragma unroll
            for (int mf = 0; mf < 2; mf++)
                ldsm_x4(ahf[mf], aB + ST_A + mf * (16 * C_ROW) + ks * 32);
#pragma unroll
            for (int p = 0; p < 4; p++) {
                uint32_t b4[4];
                ldsm_x4(b4, bB + ST_B + p * (16 * C_ROW) + ks * 32);
#pragma unroll
                for (int mf = 0; mf < 2; mf++)
#pragma unroll
                    for (int h = 0; h < 2; h++)
                        mma_fp16(acc[mf][2 * p + h], ahf[mf], &b4[h * 2]);
            }
        }
        __syncthreads();
    }

    // epilogue -> fp16
#pragma unroll
    for (int mf = 0; mf < 2; mf++) {
        int r0 = rowBase + wm * 32 + mf * 16 + (lane >> 2);
#pragma unroll
        for (int nf = 0; nf < 8; nf++) {
            int col = wn * 64 + nf * 8 + 2 * (lane & 3);
            if (r0 < M)
                *(__half2*)(g_Wh_h + (size_t)r0 * OUT_F + col) =
                    __floats2half2_rn(acc[mf][nf][0], acc[mf][nf][1]);
            if (r0 + 8 < M)
                *(__half2*)(g_Wh_h + (size_t)(r0 + 8) * OUT_F + col) =
                    __floats2half2_rn(acc[mf][nf][2], acc[mf][nf][3]);
        }
    }
}

// ---------------------------------------------------------------------------
// Kernel 2: degree histogram over src   (adj is INT32: [2, E] row-major)
// ---------------------------------------------------------------------------
__global__ void k_count(const int* __restrict__ adj, int E) {
    int e = blockIdx.x * blockDim.x + threadIdx.x;
    if (e < E) atomicAdd(&g_deg[adj[e]], 1);
}

// ---------------------------------------------------------------------------
// Kernels 3-5: exclusive scan of g_deg -> g_rowstart (and g_cursor copy)
// ---------------------------------------------------------------------------
__global__ void k_scan1(int n) {
    __shared__ int sm[SCAN_BLK];
    int i = blockIdx.x * SCAN_BLK + threadIdx.x;
    int v = (i < n) ? g_deg[i] : 0;
    sm[threadIdx.x] = v;
    __syncthreads();
    for (int off = 1; off < SCAN_BLK; off <<= 1) {
        int add = (threadIdx.x >= off) ? sm[threadIdx.x - off] : 0;
        __syncthreads();
        sm[threadIdx.x] += add;
        __syncthreads();
    }
    if (i < n) g_rowstart[i] = sm[threadIdx.x] - v;
    if (threadIdx.x == SCAN_BLK - 1) g_bsum[blockIdx.x] = sm[SCAN_BLK - 1];
}

__global__ void k_scan2(int nb) {
    __shared__ int sm[256];
    int t = threadIdx.x;
    int v = (t < nb) ? g_bsum[t] : 0;
    sm[t] = v;
    __syncthreads();
    for (int off = 1; off < 256; off <<= 1) {
        int add = (t >= off) ? sm[t - off] : 0;
        __syncthreads();
        sm[t] += add;
        __syncthreads();
    }
    if (t < nb) g_bsum[t] = sm[t] - v;
}

__global__ void k_scan3(int n) {
    int i = blockIdx.x * blockDim.x + threadIdx.x;
    if (i < n) {
        int rs = g_rowstart[i] + g_bsum[i >> 9];
        g_rowstart[i] = rs;
        g_cursor[i]   = rs;
    }
}

// ---------------------------------------------------------------------------
// Kernel 6: scatter edges into CSR (dst per slot)
// ---------------------------------------------------------------------------
__global__ void k_scatter(const int* __restrict__ adj, int E) {
    int e = blockIdx.x * blockDim.x + threadIdx.x;
    if (e < E) {
        int s = adj[e];
        int d = adj[E + e];
        int p = atomicAdd(&g_cursor[s], 1);
        g_edst[p] = d;
    }
}

// ---------------------------------------------------------------------------
// Kernel 7a: attention — 8 lanes per edge, 4 edges per warp concurrently.
// Dot over D_LABEL=32: lane holds float4; 3-level group shfl (xor 4,2,1).
// Denominator closed across groups via xor 8,16. Normalize pass re-reads
// group-leader writes via __ldcg (L2) after __syncwarp.
// ---------------------------------------------------------------------------
__global__ __launch_bounds__(256) void k_attention(
    const float* __restrict__ label,   // [N, 32]
    int n)
{
    const int wl   = threadIdx.x >> 5;
    const int lane = threadIdx.x & 31;
    const int w    = blockIdx.x * 8 + wl;
    if (w >= n) return;

    const int g = lane >> 3;   // edge group 0..3
    const int r = lane & 7;    // rank within group

    const float4 labi4 = __ldg((const float4*)(label + (size_t)w * D_LABEL) + r);
    const int start = g_rowstart[w];
    const int d     = g_deg[w];

    float denom = 0.0f;
    for (int k = 0; k < d; k += 4) {
        const int e = k + g;
        const bool valid = (e < d);
        float v = 0.0f;
        if (valid) {
            int j = __ldg(g_edst + start + e);
            float4 lj = __ldg((const float4*)(label + (size_t)j * D_LABEL) + r);
            v = labi4.x * lj.x + labi4.y * lj.y + labi4.z * lj.z + labi4.w * lj.w;
        }
        // group-local reduction (xor 4,2,1 stays within the 8-lane group)
        v += __shfl_xor_sync(0xffffffffu, v, 4);
        v += __shfl_xor_sync(0xffffffffu, v, 2);
        v += __shfl_xor_sync(0xffffffffu, v, 1);
        float ex = 0.0f;
        if (valid) {
            float le = (v >= 0.0f) ? v : ALPHA * v;
            ex = __expf(le);
            if (r == 0) g_att[start + e] = ex;
        }
        denom += ex;   // identical within group; summed across groups below
    }
    // close denominator across the 4 groups
    denom += __shfl_xor_sync(0xffffffffu, denom, 8);
    denom += __shfl_xor_sync(0xffffffffu, denom, 16);
    const float inv = 1.0f / fmaxf(denom, EPS_RS);

    __syncwarp();
    for (int t = lane; t < d; t += 32) {
        float e = __ldcg(g_att + start + t);   // L2 read: sees leader writes
        g_att[start + t] = e * inv;
    }
}

// ---------------------------------------------------------------------------
// Kernel 7b: gather — R14 exact form (best config)
// ---------------------------------------------------------------------------
__device__ __forceinline__ void fma8_h(float* acc, uint4 v, float a) {
    float2 f;
    f = __half22float2(*(__half2*)&v.x);
    acc[0] = fmaf(a, f.x, acc[0]); acc[1] = fmaf(a, f.y, acc[1]);
    f = __half22float2(*((__half2*)&v.x + 1));
    acc[2] = fmaf(a, f.x, acc[2]); acc[3] = fmaf(a, f.y, acc[3]);
    f = __half22float2(*(__half2*)&v.z);
    acc[4] = fmaf(a, f.x, acc[4]); acc[5] = fmaf(a, f.y, acc[5]);
    f = __half22float2(*((__half2*)&v.z + 1));
    acc[6] = fmaf(a, f.x, acc[6]); acc[7] = fmaf(a, f.y, acc[7]);
}

__global__ __launch_bounds__(256) void k_gather(
    float* __restrict__ out,   // [N, 256]
    int n)
{
    const int w    = blockIdx.x * 8 + (threadIdx.x >> 5);
    const int lane = threadIdx.x & 31;
    if (w >= n) return;

    const int start = g_rowstart[w];
    const int d     = g_deg[w];
    const __half* base = g_Wh_h + lane * 8;   // 16B per lane, 512B per warp row

    float acc[8];
#pragma unroll
    for (int q = 0; q < 8; q++) acc[q] = 0.0f;

    int k = 0;
    for (; k + 7 < d; k += 8) {
        int   j[8];
        float a[8];
        uint4 v[8];
#pragma unroll
        for (int u = 0; u < 8; u++) j[u] = __ldg(g_edst + start + k + u);
#pragma unroll
        for (int u = 0; u < 8; u++) a[u] = __ldg(g_att + start + k + u);
#pragma unroll
        for (int u = 0; u < 8; u++)
            v[u] = __ldg((const uint4*)(base + (size_t)j[u] * OUT_F));
#pragma unroll
        for (int u = 0; u < 8; u++) fma8_h(acc, v[u], a[u]);
    }
    for (; k + 3 < d; k += 4) {
        int j0 = __ldg(g_edst + start + k);
        int j1 = __ldg(g_edst + start + k + 1);
        int j2 = __ldg(g_edst + start + k + 2);
        int j3 = __ldg(g_edst + start + k + 3);
        float a0 = __ldg(g_att + start + k);
        float a1 = __ldg(g_att + start + k + 1);
        float a2 = __ldg(g_att + start + k + 2);
        float a3 = __ldg(g_att + start + k + 3);
        uint4 v0 = __ldg((const uint4*)(base + (size_t)j0 * OUT_F));
        uint4 v1 = __ldg((const uint4*)(base + (size_t)j1 * OUT_F));
        uint4 v2 = __ldg((const uint4*)(base + (size_t)j2 * OUT_F));
        uint4 v3 = __ldg((const uint4*)(base + (size_t)j3 * OUT_F));
        fma8_h(acc, v0, a0);
        fma8_h(acc, v1, a1);
        fma8_h(acc, v2, a2);
        fma8_h(acc, v3, a3);
    }
    for (; k < d; k++) {
        int j0 = __ldg(g_edst + start + k);
        float a0 = __ldg(g_att + start + k);
        uint4 v0 = __ldg((const uint4*)(base + (size_t)j0 * OUT_F));
        fma8_h(acc, v0, a0);
    }

    float* o = out + (size_t)w * OUT_F + lane * 8;
    __stcs((float4*)(o + 0), make_float4(acc[0], acc[1], acc[2], acc[3]));
    __stcs((float4*)(o + 4), make_float4(acc[4], acc[5], acc[6], acc[7]));
}

// ---------------------------------------------------------------------------
// Launch — stream fork: branch A = prep_W + GEMM (default stream),
//                        branch B = CSR build + attention (s2), join -> gather
// ---------------------------------------------------------------------------
extern "C" void kernel_launch(void* const* d_in, const int* in_sizes, int n_in,
                              void* d_out, int out_size)
{
    const float* h     = (const float*)d_in[0];   // [N, 256] fp32
    const float* label = (const float*)d_in[1];   // [N, 32]  fp32
    const float* W     = (const float*)d_in[2];   // [256, 256] fp32
    const int*   adj   = (const int*)d_in[3];     // [2, E] int32
    float*       out   = (float*)d_out;

    const int N = in_sizes[0] / IN_F;      // 100000
    const int E = in_sizes[3] / 2;         // 1600000

    const int T = 256;
    const int gbN = (N + T - 1) / T;
    const int gbE = (E + T - 1) / T;

    static cudaStream_t s2 = nullptr;
    static cudaEvent_t  evF = nullptr, evJ = nullptr;
    if (s2 == nullptr) {
        cudaFuncSetAttribute(k_gemm_mma, cudaFuncAttributeMaxDynamicSharedMemorySize, GSM_TOTAL);
        cudaStreamCreateWithFlags(&s2, cudaStreamNonBlocking);
        cudaEventCreateWithFlags(&evF, cudaEventDisableTiming);
        cudaEventCreateWithFlags(&evJ, cudaEventDisableTiming);
    }

    // fork
    cudaEventRecord(evF, 0);
    cudaStreamWaitEvent(s2, evF, 0);

    // ---- branch B (s2): CSR build + attention weights
    k_zero_deg<<<gbN, T, 0, s2>>>(N);
    k_count<<<gbE, T, 0, s2>>>(adj, E);
    int nb = (N + SCAN_BLK - 1) / SCAN_BLK;
    k_scan1<<<nb, SCAN_BLK, 0, s2>>>(N);
    k_scan2<<<1, 256, 0, s2>>>(nb);
    k_scan3<<<gbN, T, 0, s2>>>(N);
    k_scatter<<<gbE, T, 0, s2>>>(adj, E);
    k_attention<<<(N + 7) / 8, 256, 0, s2>>>(label, N);
    cudaEventRecord(evJ, s2);

    // ---- branch A (default stream): W prep + GEMM (R14 exact)
    k_prep_W<<<256, 256>>>(W);
    dim3 ggrid(1, (N + 127) / 128);
    k_gemm_mma<<<ggrid, 512, GSM_TOTAL>>>(h, N);

    // join, then gather
    cudaStreamWaitEvent(0, evJ, 0);
    k_gather<<<(N + 7) / 8, 256>>>(out, N);
}